// round 9
// baseline (speedup 1.0000x reference)
#include <cuda_runtime.h>
#include <cuda_bf16.h>
#include <math.h>
#include <stdint.h>

#define BB 2
#define SS 4096
#define DD 512
#define HH 8
#define HD 64
#define MROWS (BB*SS)   // 8192

typedef unsigned long long u64;
typedef unsigned int u32;

// ------------------------- device scratch ----------------------------------
__device__ float g_q[MROWS * DD];
__device__ float g_k[MROWS * DD];
__device__ float g_v[MROWS * DD];
__device__ float g_att[MROWS * DD];
__device__ __nv_bfloat16 g_qhi[MROWS * DD];
__device__ __nv_bfloat16 g_qlo[MROWS * DD];
__device__ __nv_bfloat16 g_khi[MROWS * DD];
__device__ __nv_bfloat16 g_klo[MROWS * DD];
__device__ __nv_bfloat16 g_vthi[MROWS * DD];   // layout [bh][d][s]
__device__ __nv_bfloat16 g_vtlo[MROWS * DD];
__device__ __nv_bfloat16 g_xhi[MROWS * DD];    // split of x; reused for att
__device__ __nv_bfloat16 g_xlo[MROWS * DD];
__device__ __nv_bfloat16 g_whi[4 * DD * DD];   // Wq,Wk,Wv,Wo hi
__device__ __nv_bfloat16 g_wlo[4 * DD * DD];

__device__ __forceinline__ u32 pkbf(float a, float b) {
    __nv_bfloat162 t = __floats2bfloat162_rn(a, b);   // x=a (low half)
    return *(u32*)&t;
}

// ---------------- mma.sync bf16 (baseline PTX, works on sm_103) -------------
__device__ __forceinline__ void mma16816(float* c, const u32* a, u32 b0, u32 b1) {
    asm("mma.sync.aligned.m16n8k16.row.col.f32.bf16.bf16.f32 "
        "{%0,%1,%2,%3}, {%4,%5,%6,%7}, {%8,%9}, {%0,%1,%2,%3};"
        : "+f"(c[0]), "+f"(c[1]), "+f"(c[2]), "+f"(c[3])
        : "r"(a[0]), "r"(a[1]), "r"(a[2]), "r"(a[3]), "r"(b0), "r"(b1));
}

// ---------------------------------------------------------------------------
// Generic fp32 -> bf16 (hi, lo) split.  n4 = element-count / 4.
// ---------------------------------------------------------------------------
__global__ __launch_bounds__(256) void splitf(const float* __restrict__ src,
                                              __nv_bfloat16* __restrict__ hi,
                                              __nv_bfloat16* __restrict__ lo,
                                              int n4) {
    int i = blockIdx.x * 256 + threadIdx.x;
    if (i >= n4) return;
    float4 v = ((const float4*)src)[i];
    float f[4] = {v.x, v.y, v.z, v.w};
    float h[4];
#pragma unroll
    for (int e = 0; e < 4; e++) h[e] = __bfloat162float(__float2bfloat16(f[e]));
    ((uint2*)hi)[i] = make_uint2(pkbf(h[0], h[1]), pkbf(h[2], h[3]));
    ((uint2*)lo)[i] = make_uint2(pkbf(f[0] - h[0], f[1] - h[1]),
                                 pkbf(f[2] - h[2], f[3] - h[3]));
}

// ---------------------------------------------------------------------------
// Split-bf16 HMMA GEMM: C[M x 512] = A[M x 512] * W[512 x 512]^T.
// A, W given as bf16 hi/lo (u32-paired view). 3 MMA products per tile.
// CTA 128x128, 8 warps (4m x 2n), k-chunks of 32. fp32 accumulate.
// Scalar smem stores only (st.shared.v4 into u32[] was the suspected R8 trap).
// ---------------------------------------------------------------------------
__global__ __launch_bounds__(256) void gemm_mma(const u32* __restrict__ Ahi,
                                                const u32* __restrict__ Alo,
                                                const u32* __restrict__ Whi,
                                                const u32* __restrict__ Wlo,
                                                float* __restrict__ C) {
    __shared__ __align__(16) u32 sAh[128 * 20], sAl[128 * 20];  // row stride 20 u32
    __shared__ __align__(16) u32 sWh[128 * 20], sWl[128 * 20];

    const int tid = threadIdx.x;
    const int w = tid >> 5, lane = tid & 31;
    const int g = lane >> 2, t = lane & 3;
    const int wm = w & 3, wn = w >> 2;
    const int bm = blockIdx.y * 128, bn = blockIdx.x * 128;

    float acc[2][8][4];
#pragma unroll
    for (int mf = 0; mf < 2; mf++)
#pragma unroll
        for (int n = 0; n < 8; n++)
#pragma unroll
            for (int e = 0; e < 4; e++) acc[mf][n][e] = 0.0f;

    for (int ch = 0; ch < 16; ch++) {
#pragma unroll
        for (int i = 0; i < 2; i++) {
            int idx = tid + i * 256;            // 0..511
            int r = idx >> 2, c4 = (idx & 3) * 4;
            int so = r * 20 + c4;
            size_t ga = (size_t)(bm + r) * 256 + ch * 16 + c4;
            uint4 a = *(const uint4*)(Ahi + ga);
            sAh[so] = a.x; sAh[so + 1] = a.y; sAh[so + 2] = a.z; sAh[so + 3] = a.w;
            uint4 al = *(const uint4*)(Alo + ga);
            sAl[so] = al.x; sAl[so + 1] = al.y; sAl[so + 2] = al.z; sAl[so + 3] = al.w;
            size_t gw = (size_t)(bn + r) * 256 + ch * 16 + c4;
            uint4 wh = *(const uint4*)(Whi + gw);
            sWh[so] = wh.x; sWh[so + 1] = wh.y; sWh[so + 2] = wh.z; sWh[so + 3] = wh.w;
            uint4 wl = *(const uint4*)(Wlo + gw);
            sWl[so] = wl.x; sWl[so + 1] = wl.y; sWl[so + 2] = wl.z; sWl[so + 3] = wl.w;
        }
        __syncthreads();

#pragma unroll
        for (int kb = 0; kb < 2; kb++) {
            const int ac = kb * 8 + t;
            u32 aH[2][4], aL[2][4];
#pragma unroll
            for (int mf = 0; mf < 2; mf++) {
                int r0 = (wm * 32 + mf * 16 + g) * 20;
                aH[mf][0] = sAh[r0 + ac];       aH[mf][1] = sAh[r0 + 160 + ac];
                aH[mf][2] = sAh[r0 + ac + 4];   aH[mf][3] = sAh[r0 + 160 + ac + 4];
                aL[mf][0] = sAl[r0 + ac];       aL[mf][1] = sAl[r0 + 160 + ac];
                aL[mf][2] = sAl[r0 + ac + 4];   aL[mf][3] = sAl[r0 + 160 + ac + 4];
            }
#pragma unroll
            for (int n = 0; n < 8; n++) {
                int br = (wn * 64 + n * 8 + g) * 20;
                u32 bh0 = sWh[br + ac], bh1 = sWh[br + ac + 4];
                u32 bl0 = sWl[br + ac], bl1 = sWl[br + ac + 4];
#pragma unroll
                for (int mf = 0; mf < 2; mf++) {
                    mma16816(acc[mf][n], aH[mf], bh0, bh1);
                    mma16816(acc[mf][n], aH[mf], bl0, bl1);
                    mma16816(acc[mf][n], aL[mf], bh0, bh1);
                }
            }
        }
        __syncthreads();
    }

#pragma unroll
    for (int mf = 0; mf < 2; mf++) {
        int row0 = bm + wm * 32 + mf * 16 + g;
#pragma unroll
        for (int n = 0; n < 8; n++) {
            int col = bn + wn * 64 + n * 8 + 2 * t;
            *(float2*)(C + (size_t)row0 * 512 + col)       = make_float2(acc[mf][n][0], acc[mf][n][1]);
            *(float2*)(C + (size_t)(row0 + 8) * 512 + col) = make_float2(acc[mf][n][2], acc[mf][n][3]);
        }
    }
}

// ---------------------------------------------------------------------------
// Fused axial RoPE + split: read fp32 q,k; rotate; write bf16 hi/lo only.
// q is pre-scaled by 0.125 here. One thread per (row, head, 4-dim chunk).
// ---------------------------------------------------------------------------
__global__ __launch_bounds__(256) void rope_split(const float* __restrict__ q,
                                                  const float* __restrict__ k,
                                                  __nv_bfloat16* __restrict__ qhi,
                                                  __nv_bfloat16* __restrict__ qlo,
                                                  __nv_bfloat16* __restrict__ khi,
                                                  __nv_bfloat16* __restrict__ klo) {
    int idx = blockIdx.x * 256 + threadIdx.x;
    if (idx >= MROWS * HH * 16) return;
    int c   = idx & 15;          // 4-dim chunk within head
    int rh  = idx >> 4;
    int h   = rh & 7;
    int row = rh >> 3;
    int s   = row & (SS - 1);

    int d0 = c * 4;
    float pos; int jb;
    if (d0 < 32) { pos = (float)(s >> 5); jb = c * 2; }          // t-rope
    else         { pos = (float)(s & 31); jb = (c - 8) * 2; }    // v-rope

    const float L = 13.2877123795494f / 16.0f;
    float a0 = pos * exp2f(-(float)jb * L);
    float a1 = pos * exp2f(-(float)(jb + 1) * L);
    float s0, c0, s1, c1;
    sincosf(a0, &s0, &c0);
    sincosf(a1, &s1, &c1);

    size_t base = (size_t)row * 512 + h * 64 + d0;
    int ui = (int)(base >> 2);   // uint2 index into bf16 buffers

    // q (scaled)
    {
        float4 x = *(const float4*)(q + base);
        float e0 = (x.x * c0 - x.y * s0) * 0.125f;
        float o0 = (x.x * s0 + x.y * c0) * 0.125f;
        float e1 = (x.z * c1 - x.w * s1) * 0.125f;
        float o1 = (x.z * s1 + x.w * c1) * 0.125f;
        float f[4] = {e0, o0, e1, o1}, hh[4];
#pragma unroll
        for (int e = 0; e < 4; e++) hh[e] = __bfloat162float(__float2bfloat16(f[e]));
        ((uint2*)qhi)[ui] = make_uint2(pkbf(hh[0], hh[1]), pkbf(hh[2], hh[3]));
        ((uint2*)qlo)[ui] = make_uint2(pkbf(f[0] - hh[0], f[1] - hh[1]),
                                       pkbf(f[2] - hh[2], f[3] - hh[3]));
    }
    // k
    {
        float4 x = *(const float4*)(k + base);
        float e0 = x.x * c0 - x.y * s0;
        float o0 = x.x * s0 + x.y * c0;
        float e1 = x.z * c1 - x.w * s1;
        float o1 = x.z * s1 + x.w * c1;
        float f[4] = {e0, o0, e1, o1}, hh[4];
#pragma unroll
        for (int e = 0; e < 4; e++) hh[e] = __bfloat162float(__float2bfloat16(f[e]));
        ((uint2*)khi)[ui] = make_uint2(pkbf(hh[0], hh[1]), pkbf(hh[2], hh[3]));
        ((uint2*)klo)[ui] = make_uint2(pkbf(f[0] - hh[0], f[1] - hh[1]),
                                       pkbf(f[2] - hh[2], f[3] - hh[3]));
    }
}

// ---------------------------------------------------------------------------
// Transpose + split V: v[b,s,h,d] -> vt[bh][d][s] in bf16 hi/lo.
// ---------------------------------------------------------------------------
__global__ __launch_bounds__(256) void v_split_t(const float* __restrict__ v,
                                                 __nv_bfloat16* __restrict__ vthi,
                                                 __nv_bfloat16* __restrict__ vtlo) {
    __shared__ float tile[64][65];
    const int bh = blockIdx.y;
    const int b  = bh >> 3;
    const int h  = bh & 7;
    const int s0 = blockIdx.x * 64;
    const int t  = threadIdx.x;

#pragma unroll
    for (int i = 0; i < 16; i++) {
        int idx = t + i * 256;
        int sl = idx >> 6, d = idx & 63;
        tile[sl][d] = v[((size_t)(b * SS) + s0 + sl) * DD + h * HD + d];
    }
    __syncthreads();

#pragma unroll
    for (int i = 0; i < 8; i++) {
        int j = t + i * 256;
        int d = j >> 5, sp = j & 31;
        float f0 = tile[sp * 2][d], f1 = tile[sp * 2 + 1][d];
        float hi0 = __bfloat162float(__float2bfloat16(f0));
        float hi1 = __bfloat162float(__float2bfloat16(f1));
        u32 hw = pkbf(hi0, hi1);
        u32 lw = pkbf(f0 - hi0, f1 - hi1);
        size_t o = ((((size_t)bh * HD + d) * SS + s0) >> 1) + sp;
        ((u32*)vthi)[o] = hw;
        ((u32*)vtlo)[o] = lw;
    }
}

// ---------------------------------------------------------------------------
// Flash attention on HMMA (unchanged from R7 — passed, rel_err 1.4e-5).
// ---------------------------------------------------------------------------
#define PADR 36

__global__ __launch_bounds__(256) void attn_mma(
    const __nv_bfloat16* __restrict__ qhi_, const __nv_bfloat16* __restrict__ qlo_,
    const __nv_bfloat16* __restrict__ khi_, const __nv_bfloat16* __restrict__ klo_,
    const __nv_bfloat16* __restrict__ vthi_, const __nv_bfloat16* __restrict__ vtlo_,
    float* __restrict__ out) {
    __shared__ u32 ksh_hi[64 * PADR], ksh_lo[64 * PADR];
    __shared__ u32 vsh_hi[64 * PADR], vsh_lo[64 * PADR];

    const int tid = threadIdx.x;
    const int w = tid >> 5, lane = tid & 31;
    const int g = lane >> 2, t = lane & 3;
    const int bh = blockIdx.y, b = bh >> 3, h = bh & 7;
    const int q0 = blockIdx.x * 128 + w * 16;

    const u32* qhi32 = (const u32*)qhi_;
    const u32* qlo32 = (const u32*)qlo_;
    const u32* khi32 = (const u32*)khi_;
    const u32* klo32 = (const u32*)klo_;
    const u32* vthi32 = (const u32*)vthi_;
    const u32* vtlo32 = (const u32*)vtlo_;

    u32 aQh[4][4], aQl[4][4];
    {
        const size_t rg  = (size_t)(b * SS + q0 + g) * 256 + h * 32;
        const size_t rg8 = rg + 8 * 256;
#pragma unroll
        for (int kb = 0; kb < 4; kb++) {
            aQh[kb][0] = qhi32[rg  + kb * 8 + t];
            aQh[kb][1] = qhi32[rg8 + kb * 8 + t];
            aQh[kb][2] = qhi32[rg  + kb * 8 + 4 + t];
            aQh[kb][3] = qhi32[rg8 + kb * 8 + 4 + t];
            aQl[kb][0] = qlo32[rg  + kb * 8 + t];
            aQl[kb][1] = qlo32[rg8 + kb * 8 + t];
            aQl[kb][2] = qlo32[rg  + kb * 8 + 4 + t];
            aQl[kb][3] = qlo32[rg8 + kb * 8 + 4 + t];
        }
    }

    float oacc[8][4];
#pragma unroll
    for (int j = 0; j < 8; j++)
#pragma unroll
        for (int e = 0; e < 4; e++) oacc[j][e] = 0.0f;
    float lsum0 = 0.0f, lsum1 = 0.0f;

    for (int kt = 0; kt < SS; kt += 64) {
        __syncthreads();
        {
            const size_t kg = (size_t)(b * SS + kt) * 256 + h * 32;
            const size_t vg = (size_t)bh * 64 * 2048 + (kt >> 1);
#pragma unroll
            for (int i = 0; i < 2; i++) {
                int idx = tid + i * 256;
                int s = idx >> 3, c = idx & 7;
                int so = s * PADR + c * 4;
                uint4 a = *(const uint4*)(khi32 + kg + (size_t)s * 256 + c * 4);
                ksh_hi[so] = a.x; ksh_hi[so + 1] = a.y; ksh_hi[so + 2] = a.z; ksh_hi[so + 3] = a.w;
                uint4 bq = *(const uint4*)(klo32 + kg + (size_t)s * 256 + c * 4);
                ksh_lo[so] = bq.x; ksh_lo[so + 1] = bq.y; ksh_lo[so + 2] = bq.z; ksh_lo[so + 3] = bq.w;
                uint4 cq = *(const uint4*)(vthi32 + vg + (size_t)s * 2048 + c * 4);
                vsh_hi[so] = cq.x; vsh_hi[so + 1] = cq.y; vsh_hi[so + 2] = cq.z; vsh_hi[so + 3] = cq.w;
                uint4 dq = *(const uint4*)(vtlo32 + vg + (size_t)s * 2048 + c * 4);
                vsh_lo[so] = dq.x; vsh_lo[so + 1] = dq.y; vsh_lo[so + 2] = dq.z; vsh_lo[so + 3] = dq.w;
            }
        }
        __syncthreads();

        float sacc[8][4];
#pragma unroll
        for (int j = 0; j < 8; j++)
#pragma unroll
            for (int e = 0; e < 4; e++) sacc[j][e] = 0.0f;

#pragma unroll
        for (int kb = 0; kb < 4; kb++) {
#pragma unroll
            for (int j = 0; j < 8; j++) {
                int base = (j * 8 + g) * PADR + kb * 8 + t;
                u32 bh0 = ksh_hi[base], bh1 = ksh_hi[base + 4];
                u32 bl0 = ksh_lo[base], bl1 = ksh_lo[base + 4];
                mma16816(sacc[j], aQh[kb], bh0, bh1);
                mma16816(sacc[j], aQh[kb], bl0, bl1);
                mma16816(sacc[j], aQl[kb], bh0, bh1);
            }
        }

        u32 aPh[4][4], aPl[4][4];
#pragma unroll
        for (int j = 0; j < 8; j++) {
            float p0 = __expf(sacc[j][0]);
            float p1 = __expf(sacc[j][1]);
            float p2 = __expf(sacc[j][2]);
            float p3 = __expf(sacc[j][3]);
            lsum0 += p0 + p1;
            lsum1 += p2 + p3;
            float f0 = __bfloat162float(__float2bfloat16(p0));
            float f1 = __bfloat162float(__float2bfloat16(p1));
            float f2 = __bfloat162float(__float2bfloat16(p2));
            float f3 = __bfloat162float(__float2bfloat16(p3));
            int kbp = j >> 1, r0 = (j & 1) * 2;
            aPh[kbp][r0]     = pkbf(f0, f1);
            aPh[kbp][r0 + 1] = pkbf(f2, f3);
            aPl[kbp][r0]     = pkbf(p0 - f0, p1 - f1);
            aPl[kbp][r0 + 1] = pkbf(p2 - f2, p3 - f3);
        }

#pragma unroll
        for (int kbp = 0; kbp < 4; kbp++) {
#pragma unroll
            for (int j = 0; j < 8; j++) {
                int base = (j * 8 + g) * PADR + kbp * 8 + t;
                u32 bh0 = vsh_hi[base], bh1 = vsh_hi[base + 4];
                u32 bl0 = vsh_lo[base], bl1 = vsh_lo[base + 4];
                mma16816(oacc[j], aPh[kbp], bh0, bh1);
                mma16816(oacc[j], aPh[kbp], bl0, bl1);
                mma16816(oacc[j], aPl[kbp], bh0, bh1);
            }
        }
    }

    lsum0 += __shfl_xor_sync(0xFFFFFFFFu, lsum0, 1);
    lsum0 += __shfl_xor_sync(0xFFFFFFFFu, lsum0, 2);
    lsum1 += __shfl_xor_sync(0xFFFFFFFFu, lsum1, 1);
    lsum1 += __shfl_xor_sync(0xFFFFFFFFu, lsum1, 2);
    float inv0 = 1.0f / lsum0, inv1 = 1.0f / lsum1;

    float* o0 = out + (size_t)(b * SS + q0 + g) * 512 + h * 64;
    float* o1 = o0 + 8 * 512;
#pragma unroll
    for (int j = 0; j < 8; j++) {
        *(float2*)(o0 + j * 8 + 2 * t) = make_float2(oacc[j][0] * inv0, oacc[j][1] * inv0);
        *(float2*)(o1 + j * 8 + 2 * t) = make_float2(oacc[j][2] * inv1, oacc[j][3] * inv1);
    }
}

// ---------------------------------------------------------------------------
extern "C" void kernel_launch(void* const* d_in, const int* in_sizes, int n_in,
                              void* d_out, int out_size) {
    const float* x  = (const float*)d_in[0];
    const float* Wq = (const float*)d_in[1];
    const float* Wk = (const float*)d_in[2];
    const float* Wv = (const float*)d_in[3];
    const float* Wo = (const float*)d_in[4];
    float* out = (float*)d_out;

    float *q, *k, *v, *att;
    __nv_bfloat16 *qhi, *qlo, *khi, *klo, *vthi, *vtlo, *xhi, *xlo, *whi, *wlo;
    cudaGetSymbolAddress((void**)&q,    g_q);
    cudaGetSymbolAddress((void**)&k,    g_k);
    cudaGetSymbolAddress((void**)&v,    g_v);
    cudaGetSymbolAddress((void**)&att,  g_att);
    cudaGetSymbolAddress((void**)&qhi,  g_qhi);
    cudaGetSymbolAddress((void**)&qlo,  g_qlo);
    cudaGetSymbolAddress((void**)&khi,  g_khi);
    cudaGetSymbolAddress((void**)&klo,  g_klo);
    cudaGetSymbolAddress((void**)&vthi, g_vthi);
    cudaGetSymbolAddress((void**)&vtlo, g_vtlo);
    cudaGetSymbolAddress((void**)&xhi,  g_xhi);
    cudaGetSymbolAddress((void**)&xlo,  g_xlo);
    cudaGetSymbolAddress((void**)&whi,  g_whi);
    cudaGetSymbolAddress((void**)&wlo,  g_wlo);

    const int nx4 = MROWS * DD / 4;          // x / att split size
    const int nw4 = DD * DD / 4;             // one weight split size

    // Split inputs to bf16 hi/lo
    splitf<<<(nx4 + 255) / 256, 256>>>(x, xhi, xlo, nx4);
    splitf<<<(nw4 + 255) / 256, 256>>>(Wq, whi + 0 * DD * DD, wlo + 0 * DD * DD, nw4);
    splitf<<<(nw4 + 255) / 256, 256>>>(Wk, whi + 1 * DD * DD, wlo + 1 * DD * DD, nw4);
    splitf<<<(nw4 + 255) / 256, 256>>>(Wv, whi + 2 * DD * DD, wlo + 2 * DD * DD, nw4);
    splitf<<<(nw4 + 255) / 256, 256>>>(Wo, whi + 3 * DD * DD, wlo + 3 * DD * DD, nw4);

    dim3 ggrid(512 / 128, MROWS / 128);      // (4, 64)
    const u32* xh32 = (const u32*)xhi;  const u32* xl32 = (const u32*)xlo;
    const u32* wh32 = (const u32*)whi;  const u32* wl32 = (const u32*)wlo;
    const int WSTRIDE = DD * DD / 2;         // u32 elements per weight

    gemm_mma<<<ggrid, 256>>>(xh32, xl32, wh32 + 0 * WSTRIDE, wl32 + 0 * WSTRIDE, q);
    gemm_mma<<<ggrid, 256>>>(xh32, xl32, wh32 + 1 * WSTRIDE, wl32 + 1 * WSTRIDE, k);
    gemm_mma<<<ggrid, 256>>>(xh32, xl32, wh32 + 2 * WSTRIDE, wl32 + 2 * WSTRIDE, v);

    // Fused RoPE + scale + bf16 split for q, k
    int nch = MROWS * HH * 16;
    rope_split<<<(nch + 255) / 256, 256>>>(q, k, qhi, qlo, khi, klo);

    v_split_t<<<dim3(SS / 64, BB * HH), 256>>>(v, vthi, vtlo);

    attn_mma<<<dim3(SS / 128, BB * HH), 256>>>(qhi, qlo, khi, klo, vthi, vtlo, att);

    // Split att (reuse x split buffers) and final projection
    splitf<<<(nx4 + 255) / 256, 256>>>(att, xhi, xlo, nx4);
    gemm_mma<<<ggrid, 256>>>(xh32, xl32, wh32 + 3 * WSTRIDE, wl32 + 3 * WSTRIDE, out);
}